// round 3
// baseline (speedup 1.0000x reference)
#include <cuda_runtime.h>
#include <cstdint>

#define FM 0xffffffffu
#define NW 32
#define INFV 1000000000.0f

// order-preserving float <-> uint maps (monotonic)
__device__ __forceinline__ unsigned ford(float f) {
    unsigned u = __float_as_uint(f);
    return u ^ (unsigned)(((int)u >> 31) | 0x80000000);
}
__device__ __forceinline__ float iford(unsigned k) {
    unsigned u = k ^ (unsigned)(((int)(~k) >> 31) | 0x80000000);
    return __uint_as_float(u);
}

struct Feat {
    float cx, cy, area, sr, ar, bx, by, prob;
};

__device__ __forceinline__ Feat wall_features(const float* __restrict__ q) {
    float sx = q[0], sy = q[1], ex = q[2], ey = q[3], w = q[4], prob = q[5];
    float dx = ex - sx, dy = ey - sy;
    float len = sqrtf(dx * dx + dy * dy);
    float cx = (sx + ex) * 0.5f, cy = (sy + ey) * 0.5f;
    float area = len * w;
    float smaller = fminf(w, len), bigger = fmaxf(w, len);
    float sr = (bigger > 0.0f) ? (smaller / bigger) : 0.0f;
    float px, py;
    if (len > 0.0f) {
        float s = w * 0.5f / len;
        px = dy * s;
        py = -dx * s;
    } else {
        px = 0.0f;
        py = 0.0f;
    }
    float right = fmaxf(fmaxf(sx + px, sx - px), fmaxf(ex + px, ex - px));
    float top   = fmaxf(fmaxf(sy + py, sy - py), fmaxf(ey + py, ey - py));
    float bbw = fabsf((right - cx) * 2.0f);
    float bbh = fabsf((top  - cy) * 2.0f);
    float bba = bbw * bbh;
    float ar = (bba > 0.001f) ? (area / bba) : 1.0f;
    Feat f;
    f.cx = cx; f.cy = cy; f.area = area; f.sr = sr; f.ar = ar;
    f.bx = bbw; f.by = bbh; f.prob = prob;
    return f;
}

// One warp per batch; columns (pred walls) <-> lanes.
// LAPJV: column reduction + augmenting row reduction + shortest augmenting paths.
__global__ void __launch_bounds__(32)
floorplanet_kernel(const float* __restrict__ params_true,
                   const float* __restrict__ params_pred,
                   float* __restrict__ out) {
    __shared__ float C[NW * NW];
    __shared__ int c4r_sh[NW];

    const int b = blockIdx.x;
    const int lane = threadIdx.x;

    Feat ft = wall_features(params_true + (size_t)b * NW * 6 + lane * 6);
    Feat fp = wall_features(params_pred + (size_t)b * NW * 6 + lane * 6);

    // Fill C[i][lane]; track column min/argmin.
    float cm = INFV;
    int am = 0;
#pragma unroll 4
    for (int i = 0; i < NW; i++) {
        float icx   = __shfl_sync(FM, ft.cx,   i);
        float icy   = __shfl_sync(FM, ft.cy,   i);
        float iarea = __shfl_sync(FM, ft.area, i);
        float isr   = __shfl_sync(FM, ft.sr,   i);
        float iar   = __shfl_sync(FM, ft.ar,   i);
        float ibx   = __shfl_sync(FM, ft.bx,   i);
        float iby   = __shfl_sync(FM, ft.by,   i);
        float iprob = __shfl_sync(FM, ft.prob, i);

        float dcx = icx - fp.cx, dcy = icy - fp.cy;
        float center_d = dcx * dcx + dcy * dcy;
        float da = iarea - fp.area;
        float ds = isr   - fp.sr;
        float dr = iar   - fp.ar;
        float dh = ibx   - fp.bx;
        float dv = iby   - fp.by;
        float dp = iprob - fp.prob;

        float param_d = da * da + center_d + dr * dr + dh * dh + dv * dv + ds * ds;
        float cost = 10.0f * (dp * dp) + param_d * iprob;
        C[i * NW + lane] = cost;
        if (cost < cm) { cm = cost; am = i; }
    }
    __syncwarp();

    // ---- Phase 1: column reduction. v[j]=colmin, greedily match argmin rows.
    float v = cm, u = 0.0f;
    unsigned grp = __match_any_sync(FM, am);
    bool winner = ((__ffs(grp) - 1) == lane);
    int row4col = winner ? am : -1;
    c4r_sh[lane] = -1;
    __syncwarp();
    if (winner) c4r_sh[am] = lane;
    __syncwarp();
    int col4row = c4r_sh[lane];
    unsigned freerows = __ballot_sync(FM, col4row < 0);

    // ---- Phase 2: augmenting row reduction with kick chains.
    unsigned sap = 0u;        // rows deferred to SAP
    int guard = 96;
    while (freerows) {
        int i = __ffs(freerows) - 1;
        freerows &= freerows - 1;
        while (i >= 0) {
            if (--guard < 0) { sap |= 1u << i; break; }
            float d = C[i * NW + lane] - v;
            unsigned k = (ford(d) & ~31u) | (unsigned)lane;
            unsigned m1 = __reduce_min_sync(FM, k);
            int j1 = m1 & 31;
            unsigned k2 = (lane == j1) ? 0xFFFFFFFFu : k;
            unsigned m2 = __reduce_min_sync(FM, k2);
            unsigned q1 = m1 & ~31u, q2 = m2 & ~31u;
            int i1 = __shfl_sync(FM, row4col, j1);
            if (q1 < q2) {
                float u1 = iford(q1), u2 = iford(q2);
                if (lane == j1) { v -= (u2 - u1); row4col = i; }
                if (lane == i)  { u = u2; col4row = j1; }
                if (i1 >= 0) {
                    if (lane == i1) col4row = -1;
                    i = i1;            // kicked row continues the chain
                } else {
                    i = -1;
                }
            } else {                   // quantized tie
                int j2 = m2 & 31;
                int i2 = __shfl_sync(FM, row4col, j2);
                float u1 = iford(q1);
                if (i1 < 0) {
                    if (lane == i)  { u = u1; col4row = j1; }
                    if (lane == j1) row4col = i;
                    i = -1;
                } else if (i2 < 0) {
                    if (lane == i)  { u = u1; col4row = j2; }
                    if (lane == j2) row4col = i;
                    i = -1;
                } else {
                    sap |= 1u << i;    // defer to SAP
                    i = -1;
                }
            }
        }
    }

    // ---- Phase 3: shortest augmenting path for remaining free rows.
    while (sap) {
        const int i0 = __ffs(sap) - 1;
        sap &= sap - 1;

        float ur = __shfl_sync(FM, u, row4col & 31);  // u[row4col[lane]]
        float ui = __shfl_sync(FM, u, i0);
        unsigned SR = 0u, SC = 0u;
        float spc = INFV;
        unsigned mkey = 0xFFFFFFFFu;
        int path = -1;
        float minVal = 0.0f;
        float mvv = -v;
        int i = i0, sink = -1;

        do {
            SR |= 1u << i;
            float slack = (C[i * NW + lane] - ui) + mvv;
            bool notSC = ((SC >> lane) & 1u) == 0u;
            unsigned skey = notSC ? ((ford(slack) & ~31u) | (unsigned)lane)
                                  : 0xFFFFFFFFu;
            if (skey < mkey) { mkey = skey; spc = iford(skey & ~31u); path = i; }

            unsigned om = __reduce_min_sync(FM, mkey);   // min + argmin in one
            int j = om & 31;
            minVal = iford(om & ~31u);
            mvv = minVal - v;
            SC |= 1u << j;
            if (lane == j) mkey = 0xFFFFFFFFu;           // spc stays frozen
            int r     = __shfl_sync(FM, row4col, j);     // independent pair:
            float urj = __shfl_sync(FM, ur, j);          // overlapping shfls
            if (r < 0) sink = j;
            i = r;
            ui = urj;
        } while (sink < 0);

        // Dual updates.
        float spc_c4r = __shfl_sync(FM, spc, col4row & 31);
        if ((SR >> lane) & 1u) u += (lane == i0) ? minVal : (minVal - spc_c4r);
        if ((SC >> lane) & 1u) v -= minVal - spc;

        // Augment along alternating path.
        int j = sink;
        bool done = false;
        while (!done) {
            int pi = __shfl_sync(FM, path, j);
            if (lane == j) row4col = pi;
            int jn = __shfl_sync(FM, col4row, pi);
            if (lane == pi) col4row = j;
            done = (pi == i0);
            j = jn;
        }
    }

    // loss = sum_i C[i][col4row[i]]
    float c = C[lane * NW + (col4row & 31)];
#pragma unroll
    for (int off = 16; off > 0; off >>= 1)
        c += __shfl_xor_sync(FM, c, off);
    if (lane == 0) out[b] = c;
}

extern "C" void kernel_launch(void* const* d_in, const int* in_sizes, int n_in,
                              void* d_out, int out_size) {
    const float* params_true = (const float*)d_in[0];
    const float* params_pred = (const float*)d_in[1];
    float* out = (float*)d_out;
    (void)in_sizes; (void)n_in; (void)out_size;
    floorplanet_kernel<<<2048, 32>>>(params_true, params_pred, out);
}

// round 4
// speedup vs baseline: 1.5217x; 1.5217x over previous
#include <cuda_runtime.h>
#include <cstdint>

#define FM 0xffffffffu
#define NW 32
#define INFV 1000000000.0f
#define KMASK 0xFFFFFFE0u   // key mask: high 27 bits slack, low 5 bits lane

struct Feat {
    float cx, cy, area, sr, ar, bx, by, prob;
};

__device__ __forceinline__ Feat wall_features(const float* __restrict__ q) {
    float sx = q[0], sy = q[1], ex = q[2], ey = q[3], w = q[4], prob = q[5];
    float dx = ex - sx, dy = ey - sy;
    float len = sqrtf(dx * dx + dy * dy);
    float cx = (sx + ex) * 0.5f, cy = (sy + ey) * 0.5f;
    float area = len * w;
    float smaller = fminf(w, len), bigger = fmaxf(w, len);
    float sr = (bigger > 0.0f) ? (smaller / bigger) : 0.0f;
    float px, py;
    if (len > 0.0f) {
        float s = w * 0.5f / len;
        px = dy * s;
        py = -dx * s;
    } else {
        px = 0.0f;
        py = 0.0f;
    }
    float right = fmaxf(fmaxf(sx + px, sx - px), fmaxf(ex + px, ex - px));
    float top   = fmaxf(fmaxf(sy + py, sy - py), fmaxf(ey + py, ey - py));
    float bbw = fabsf((right - cx) * 2.0f);
    float bbh = fabsf((top  - cy) * 2.0f);
    float bba = bbw * bbh;
    float ar = (bba > 0.001f) ? (area / bba) : 1.0f;
    Feat f;
    f.cx = cx; f.cy = cy; f.area = area; f.sr = sr; f.ar = ar;
    f.bx = bbw; f.by = bbh; f.prob = prob;
    return f;
}

// One warp per batch; columns (pred walls) <-> lanes.
// JV: column reduction + kick-free free-row pass + shortest augmenting paths.
// All slacks are >= 0 (clamped), so raw float bits are uint-order-preserving:
// keys = (float_bits & KMASK) | lane, min+argmin in one __reduce_min_sync.
__global__ void __launch_bounds__(32)
floorplanet_kernel(const float* __restrict__ params_true,
                   const float* __restrict__ params_pred,
                   float* __restrict__ out) {
    __shared__ float C[NW * NW];
    __shared__ int c4r_sh[NW];

    const int b = blockIdx.x;
    const int lane = threadIdx.x;

    Feat ft = wall_features(params_true + (size_t)b * NW * 6 + lane * 6);
    Feat fp = wall_features(params_pred + (size_t)b * NW * 6 + lane * 6);

    // Fill C[i][lane]; track column min on the fly.
    float cm = INFV;
    int am = 0;
#pragma unroll 4
    for (int i = 0; i < NW; i++) {
        float icx   = __shfl_sync(FM, ft.cx,   i);
        float icy   = __shfl_sync(FM, ft.cy,   i);
        float iarea = __shfl_sync(FM, ft.area, i);
        float isr   = __shfl_sync(FM, ft.sr,   i);
        float iar   = __shfl_sync(FM, ft.ar,   i);
        float ibx   = __shfl_sync(FM, ft.bx,   i);
        float iby   = __shfl_sync(FM, ft.by,   i);
        float iprob = __shfl_sync(FM, ft.prob, i);

        float dcx = icx - fp.cx, dcy = icy - fp.cy;
        float center_d = dcx * dcx + dcy * dcy;
        float da = iarea - fp.area;
        float ds = isr   - fp.sr;
        float dr = iar   - fp.ar;
        float dh = ibx   - fp.bx;
        float dv = iby   - fp.by;
        float dp = iprob - fp.prob;

        float param_d = da * da + center_d + dr * dr + dh * dh + dv * dv + ds * ds;
        float cost = 10.0f * (dp * dp) + param_d * iprob;
        C[i * NW + lane] = cost;
        if (cost < cm) { cm = cost; am = i; }
    }
    __syncwarp();

    // ---- Phase 1: column reduction. v[j]=colmin, greedily match argmin rows.
    float v = cm, u = 0.0f;
    unsigned grp = __match_any_sync(FM, am);
    bool winner = ((__ffs(grp) - 1) == lane);
    int row4col = winner ? am : -1;
    c4r_sh[lane] = -1;
    __syncwarp();
    if (winner) c4r_sh[am] = lane;
    __syncwarp();
    int col4row = c4r_sh[lane];
    unsigned freerows = __ballot_sync(FM, col4row < 0);

    // ---- Phase 2': kick-free free-row pass. Each free row takes its argmin
    // column iff that column is unmatched; otherwise it just keeps the
    // (feasible) dual u[i] = min reduced cost and stays free for SAP.
    unsigned rem = freerows;
    while (rem) {
        const int i = __ffs(rem) - 1;
        rem &= rem - 1;
        float d = fmaxf(C[i * NW + lane] - v, 0.0f);
        unsigned k = (__float_as_uint(d) & KMASK) | (unsigned)lane;
        unsigned m = __reduce_min_sync(FM, k);
        int j = m & 31;
        int r = __shfl_sync(FM, row4col, j);
        float umin = __uint_as_float(m & KMASK);
        if (lane == i) u = umin;           // feasible dual, rounded down
        if (r < 0) {                        // column free -> match
            if (lane == j) row4col = i;
            if (lane == i) col4row = j;
            freerows &= ~(1u << i);
        }
    }

    // ---- Phase 3: shortest augmenting path for remaining free rows.
    while (freerows) {
        const int i0 = __ffs(freerows) - 1;
        freerows &= freerows - 1;

        float ur = __shfl_sync(FM, u, row4col & 31);  // u[row4col[lane]]
        float ui = __shfl_sync(FM, u, i0);
        unsigned SR = 0u, SC = 0u;
        unsigned mkey = 0xFFFFFFFFu;
        unsigned laneor = (unsigned)lane;   // becomes ~0 once lane enters SC
        float spc = INFV;
        int path = -1;
        float minVal = 0.0f;
        float sub = ui + v;                 // slack = C - sub (minVal folded in)
        int i = i0, sink = -1;

        do {
            SR |= 1u << i;
            float slack = fmaxf(C[i * NW + lane] - sub, 0.0f);
            unsigned skey = (__float_as_uint(slack) & KMASK) | laneor;
            if (skey < mkey) {              // off-chain: feeds post-loop only
                spc = __uint_as_float(skey & KMASK);
                path = i;
            }
            mkey = umin(mkey, skey);
            unsigned om = __reduce_min_sync(FM, mkey);
            int j = om & 31;
            minVal = __uint_as_float(om & KMASK);
            SC |= 1u << j;
            if (lane == j) { laneor = 0xFFFFFFFFu; mkey = 0xFFFFFFFFu; }
            int r     = __shfl_sync(FM, row4col, j);   // overlapping shfls
            float urj = __shfl_sync(FM, ur, j);
            sub = urj + v - minVal;         // in shfl shadow
            if (r < 0) sink = j;
            i = r;
        } while (sink < 0);

        // Dual updates (spc frozen at selection for SC lanes).
        float spc_c4r = __shfl_sync(FM, spc, col4row & 31);
        if ((SR >> lane) & 1u) u += (lane == i0) ? minVal : (minVal - spc_c4r);
        if ((SC >> lane) & 1u) v -= minVal - spc;

        // Augment along alternating path.
        int j = sink;
        bool done = false;
        while (!done) {
            int pi = __shfl_sync(FM, path, j);
            if (lane == j) row4col = pi;
            int jn = __shfl_sync(FM, col4row, pi);
            if (lane == pi) col4row = j;
            done = (pi == i0);
            j = jn;
        }
    }

    // loss = sum_i C[i][col4row[i]]
    float c = C[lane * NW + (col4row & 31)];
#pragma unroll
    for (int off = 16; off > 0; off >>= 1)
        c += __shfl_xor_sync(FM, c, off);
    if (lane == 0) out[b] = c;
}

extern "C" void kernel_launch(void* const* d_in, const int* in_sizes, int n_in,
                              void* d_out, int out_size) {
    const float* params_true = (const float*)d_in[0];
    const float* params_pred = (const float*)d_in[1];
    float* out = (float*)d_out;
    (void)in_sizes; (void)n_in; (void)out_size;
    floorplanet_kernel<<<2048, 32>>>(params_true, params_pred, out);
}